// round 11
// baseline (speedup 1.0000x reference)
#include <cuda_runtime.h>
#include <cuda_fp16.h>
#include <cstdint>

#define KC   512
#define DD   64
#define TPB  256
#define BN   128
#define LDA  72
#define ROWB 144

// smem: A tiles + double-buffered B quarters (H+M+hww) + mbarriers
#define OFF_AH   0                     // 128 x 144B
#define OFF_AM   18432                 // 128 x 144B
#define OFF_BB   36864                 // 2 bufs x BUFSZ
#define BUFSZ    37376                 // H 18432 + M 18432 + hww 512
#define OFF_MB   (OFF_BB + 2 * BUFSZ)  // 111616: full0 full1 empty0 empty1 (8B each)
#define SMEM_TOTAL (OFF_MB + 128)      // 111744 B -> 2 CTAs/SM (223488 < 228K)
// post-loop overlay (inside OFF_BB region, after final syncthreads)
#define OFF_SBV  (OFF_BB)              // 128x2 f32
#define OFF_SBI  (OFF_BB + 1024)       // 128x2 i32
#define OFF_KIDX (OFF_BB + 2048)       // 128 i32
#define OFF_SRED (OFF_BB + 2560)       // 8 dbl

__device__ __align__(16) __half g_bh[KC * LDA];    // fp16 h of codebook [k][d]
__device__ __align__(16) __half g_bm[KC * LDA];    // fp16 m of codebook
__device__ __align__(16) float  g_embT[KC * DD];   // fp32 codebook [k][d]
__device__ __align__(16) float  g_hww[KC];         // 0.5*||w||^2
__device__ double   g_loss_sum;
__device__ unsigned g_ctr;

#define LDSM4(r0, r1, r2, r3, addr) \
    asm volatile("ldmatrix.sync.aligned.m8n8.x4.shared.b16 {%0,%1,%2,%3}, [%4];" \
                 : "=r"(r0), "=r"(r1), "=r"(r2), "=r"(r3) : "r"(addr))

#define MMA(d, a, b) \
    asm volatile("mma.sync.aligned.m16n8k16.row.col.f32.f16.f16.f32 " \
                 "{%0,%1,%2,%3}, {%4,%5,%6,%7}, {%8,%9}, {%0,%1,%2,%3};" \
                 : "+f"((d)[0]), "+f"((d)[1]), "+f"((d)[2]), "+f"((d)[3]) \
                 : "r"((a)[0]), "r"((a)[1]), "r"((a)[2]), "r"((a)[3]), \
                   "r"((b)[0]), "r"((b)[1]))

#define CPA16(dst, src) \
    asm volatile("cp.async.cg.shared.global [%0], [%1], 16;" :: "r"(dst), "l"(src))

// wait for phase `parity` completion (proven-compiling form from R3)
#define MBAR_WAIT(mbar, parity) do {                                           \
    asm volatile(                                                              \
        "{\n\t.reg .pred P;\n\t"                                               \
        "WL_%=:\n\t"                                                           \
        "mbarrier.try_wait.parity.acquire.cta.shared::cta.b64 P, [%0], %1, 0x989680;\n\t" \
        "@P bra.uni WD_%=;\n\t"                                                \
        "bra.uni WL_%=;\n\t"                                                   \
        "WD_%=:\n\t}"                                                          \
        :: "r"(mbar), "r"(parity) : "memory");                                 \
} while (0)

// ---- pre: emb [64][512] -> g_bh/g_bm (fp16 h/m [k][d]), g_embT (fp32), g_hww ----
__global__ void __launch_bounds__(128)
vq_pre_kernel(const float* __restrict__ emb)
{
    __shared__ float sp[4][32];
    const int t = threadIdx.x;
    const int c = blockIdx.x * 32 + (t & 31);
    const int dseg = (t >> 5) * 16;

    float e[16];
    uint32_t hw[8], mw[8];
    float s = 0.f;
    #pragma unroll
    for (int j = 0; j < 8; j++) {
        float e0 = __ldg(emb + (size_t)(dseg + 2 * j) * KC + c);
        float e1 = __ldg(emb + (size_t)(dseg + 2 * j + 1) * KC + c);
        e[2 * j] = e0; e[2 * j + 1] = e1;
        s = fmaf(e1, e1, fmaf(e0, e0, s));
        __half h0 = __float2half_rn(e0), h1 = __float2half_rn(e1);
        __half m0 = __float2half_rn(e0 - __half2float(h0));
        __half m1 = __float2half_rn(e1 - __half2float(h1));
        hw[j] = (uint32_t)__half_as_ushort(h0) | ((uint32_t)__half_as_ushort(h1) << 16);
        mw[j] = (uint32_t)__half_as_ushort(m0) | ((uint32_t)__half_as_ushort(m1) << 16);
    }
    *(uint4*)(g_bh + c * LDA + dseg)     = make_uint4(hw[0], hw[1], hw[2], hw[3]);
    *(uint4*)(g_bh + c * LDA + dseg + 8) = make_uint4(hw[4], hw[5], hw[6], hw[7]);
    *(uint4*)(g_bm + c * LDA + dseg)     = make_uint4(mw[0], mw[1], mw[2], mw[3]);
    *(uint4*)(g_bm + c * LDA + dseg + 8) = make_uint4(mw[4], mw[5], mw[6], mw[7]);
    float* et = g_embT + (size_t)c * DD + dseg;
    #pragma unroll
    for (int j = 0; j < 4; j++)
        *(float4*)(et + 4 * j) = make_float4(e[4 * j], e[4 * j + 1], e[4 * j + 2], e[4 * j + 3]);
    sp[t >> 5][t & 31] = s;
    __syncthreads();
    if (t < 32)
        g_hww[blockIdx.x * 32 + t] = 0.5f * (sp[0][t] + sp[1][t] + sp[2][t] + sp[3][t]);
}

// copy quarter qtr into buffer buf; each thread arrives (.noinc) when its copies land
__device__ __forceinline__ void produce(uint32_t sb, int qtr, int buf, int t)
{
    const char* srcH = (const char*)g_bh + (size_t)qtr * 128 * ROWB;
    const char* srcM = (const char*)g_bm + (size_t)qtr * 128 * ROWB;
    const uint32_t dst = sb + OFF_BB + buf * BUFSZ;
    #pragma unroll
    for (int i = t; i < 1152; i += TPB) {           // 128*144B/16 per term
        CPA16(dst + i * 16, srcH + i * 16);
        CPA16(dst + 18432 + i * 16, srcM + i * 16);
    }
    if (t < 32) CPA16(dst + 36864 + t * 16, (const char*)g_hww + qtr * 512 + t * 16);
    asm volatile("cp.async.mbarrier.arrive.noinc.shared.b64 [%0];"
                 :: "r"(sb + OFF_MB + buf * 8) : "memory");
}

__global__ void __launch_bounds__(TPB, 2)
vq_main_kernel(const float* __restrict__ x, float* __restrict__ out_q,
               float* __restrict__ out_idx, float* __restrict__ out_loss,
               int n_rows, double inv_count)
{
    extern __shared__ char smem[];
    const uint32_t sb = (uint32_t)__cvta_generic_to_shared(smem);
    const int t = threadIdx.x, lane = t & 31, w = t >> 5;
    const int wm = w >> 1, wn = w & 1;       // 4 m-warps x 2 n-warps
    const int rowbase = blockIdx.x * BN;

    if (t == 0) {
        asm volatile("mbarrier.init.shared.b64 [%0], %1;" :: "r"(sb + OFF_MB + 0),  "r"(256u) : "memory");
        asm volatile("mbarrier.init.shared.b64 [%0], %1;" :: "r"(sb + OFF_MB + 8),  "r"(256u) : "memory");
        asm volatile("mbarrier.init.shared.b64 [%0], %1;" :: "r"(sb + OFF_MB + 16), "r"(8u)   : "memory");
        asm volatile("mbarrier.init.shared.b64 [%0], %1;" :: "r"(sb + OFF_MB + 24), "r"(8u)   : "memory");
    }
    __syncthreads();

    // prologue: fill both buffers (async; .noinc arrivals on full[0], full[1])
    produce(sb, 0, 0, t);
    produce(sb, 1, 1, t);

    // ---- A split: x -> h (AH) + m (AM) fp16 tiles (overlaps the copies) ----
    {
        const int row = t >> 1, hseg = (t & 1) * 32;
        const bool valid = (rowbase + row) < n_rows;
        const float4* xr = (const float4*)(x + (size_t)(rowbase + row) * DD + hseg);
        __half* ah = (__half*)(smem + OFF_AH) + row * LDA + hseg;
        __half* am = (__half*)(smem + OFF_AM) + row * LDA + hseg;
        #pragma unroll
        for (int j = 0; j < 8; j++) {
            float4 f = valid ? xr[j] : make_float4(0.f, 0.f, 0.f, 0.f);
            float e[4] = {f.x, f.y, f.z, f.w};
            __half h[4], m[4];
            #pragma unroll
            for (int p = 0; p < 4; p++) {
                h[p] = __float2half_rn(e[p]);
                m[p] = __float2half_rn(e[p] - __half2float(h[p]));
            }
            *(__half2*)(ah + 4 * j)     = __halves2half2(h[0], h[1]);
            *(__half2*)(ah + 4 * j + 2) = __halves2half2(h[2], h[3]);
            *(__half2*)(am + 4 * j)     = __halves2half2(m[0], m[1]);
            *(__half2*)(am + 4 * j + 2) = __halves2half2(m[2], m[3]);
        }
    }
    __syncthreads();   // A tiles visible to all warps' ldmatrix

    float best[4];
    int   bk[4];
    #pragma unroll
    for (int s = 0; s < 4; s++) { best[s] = -3.402823466e38f; bk[s] = 0; }

    const uint32_t a_off = (uint32_t)((wm * 32 + (lane & 15)) * ROWB + (((lane >> 4) << 3) << 1));
    const uint32_t b_off = (uint32_t)(((lane & 7) + ((lane >> 4) << 3) + wn * 64) * ROWB
                                      + ((((lane >> 3) & 1) << 3) << 1));

    #pragma unroll 1
    for (int q = 0; q < 4; q++) {
        const int buf = q & 1;
        const int par = (q >> 1) & 1;
        const uint32_t bbase = sb + OFF_BB + buf * BUFSZ;
        const uint32_t fullb = sb + OFF_MB + buf * 8;
        const uint32_t emptyb = sb + OFF_MB + 16 + buf * 8;

        MBAR_WAIT(fullb, par);   // B quarter data + hww resident

        // ---- 3-term MMA: acc = hH + mH + hM - 0.5||w||^2 ----
        float acc[2][8][4];
        {
            const float* hww = (const float*)(smem + OFF_BB + buf * BUFSZ + 36864);
            #pragma unroll
            for (int nt = 0; nt < 8; nt++) {
                float2 hv = *(const float2*)(hww + wn * 64 + nt * 8 + 2 * (lane & 3));
                #pragma unroll
                for (int mt = 0; mt < 2; mt++) {
                    acc[mt][nt][0] = -hv.x; acc[mt][nt][1] = -hv.y;
                    acc[mt][nt][2] = -hv.x; acc[mt][nt][3] = -hv.y;
                }
            }
        }
        #pragma unroll
        for (int kc = 0; kc < 4; kc++) {
            const uint32_t ka = (uint32_t)(kc * 32);
            uint32_t ah[2][4], am[2][4], bb[8][2];
            LDSM4(ah[0][0], ah[0][1], ah[0][2], ah[0][3], sb + OFF_AH + a_off + ka);
            LDSM4(ah[1][0], ah[1][1], ah[1][2], ah[1][3], sb + OFF_AH + a_off + ka + 16 * ROWB);
            LDSM4(am[0][0], am[0][1], am[0][2], am[0][3], sb + OFF_AM + a_off + ka);
            LDSM4(am[1][0], am[1][1], am[1][2], am[1][3], sb + OFF_AM + a_off + ka + 16 * ROWB);
            #pragma unroll
            for (int ng = 0; ng < 4; ng++)
                LDSM4(bb[2 * ng][0], bb[2 * ng][1], bb[2 * ng + 1][0], bb[2 * ng + 1][1],
                      bbase + b_off + ka + ng * 16 * ROWB);
            #pragma unroll
            for (int mt = 0; mt < 2; mt++)
                #pragma unroll
                for (int nt = 0; nt < 8; nt++) {
                    MMA(acc[mt][nt], ah[mt], bb[nt]);   // h.H
                    MMA(acc[mt][nt], am[mt], bb[nt]);   // m.H
                }
            #pragma unroll
            for (int ng = 0; ng < 4; ng++)
                LDSM4(bb[2 * ng][0], bb[2 * ng][1], bb[2 * ng + 1][0], bb[2 * ng + 1][1],
                      bbase + 18432 + b_off + ka + ng * 16 * ROWB);
            #pragma unroll
            for (int mt = 0; mt < 2; mt++)
                #pragma unroll
                for (int nt = 0; nt < 8; nt++)
                    MMA(acc[mt][nt], ah[mt], bb[nt]);   // h.M
        }

        // this warp is done reading buffer buf
        if (lane == 0)
            asm volatile("mbarrier.arrive.shared.b64 _, [%0];" :: "r"(emptyb) : "memory");

        // ---- scan (register-local; laggard warps drain meanwhile) ----
        #pragma unroll
        for (int mt = 0; mt < 2; mt++)
            #pragma unroll
            for (int nt = 0; nt < 8; nt++) {
                const int c0 = q * 128 + wn * 64 + nt * 8 + 2 * (lane & 3);
                #pragma unroll
                for (int rh = 0; rh < 2; rh++) {
                    const int s = mt * 2 + rh;
                    float v0 = acc[mt][nt][rh * 2 + 0];
                    float v1 = acc[mt][nt][rh * 2 + 1];
                    if (v0 > best[s]) { best[s] = v0; bk[s] = c0; }
                    if (v1 > best[s]) { best[s] = v1; bk[s] = c0 + 1; }
                }
            }

        // ---- refill this buffer with quarter q+2 once all warps have read it ----
        if (q < 2) {
            MBAR_WAIT(emptyb, par);
            produce(sb, q + 2, buf, t);
        }
    }
    __syncthreads();   // everyone past all B reads -> overlay scratch on OFF_BB

    // ---- per-row reduce: width-4 shfl, then combine the 2 n-warps ----
    #pragma unroll
    for (int s = 0; s < 4; s++) {
        float v = best[s]; int bi = bk[s];
        #pragma unroll
        for (int off = 1; off <= 2; off <<= 1) {
            float ov = __shfl_xor_sync(0xffffffffu, v, off);
            int   oi = __shfl_xor_sync(0xffffffffu, bi, off);
            if (ov > v || (ov == v && oi < bi)) { v = ov; bi = oi; }
        }
        if ((lane & 3) == 0) {
            int row = wm * 32 + (s >> 1) * 16 + (s & 1) * 8 + (lane >> 2);
            ((float*)(smem + OFF_SBV))[row * 2 + wn] = v;
            ((int*)(smem + OFF_SBI))[row * 2 + wn] = bi;
        }
    }
    __syncthreads();
    if (t < 128) {
        float v0 = ((float*)(smem + OFF_SBV))[t * 2 + 0];
        float v1 = ((float*)(smem + OFF_SBV))[t * 2 + 1];
        int   i0 = ((int*)(smem + OFF_SBI))[t * 2 + 0];
        int   i1 = ((int*)(smem + OFF_SBI))[t * 2 + 1];
        int k = (v1 > v0 || (v1 == v0 && i1 < i0)) ? i1 : i0;
        ((int*)(smem + OFF_KIDX))[t] = k;
        if (rowbase + t < n_rows) out_idx[rowbase + t] = (float)k;
    }
    __syncthreads();

    // ---- epilogue: q from g_embT (exact fp32), loss vs x re-read ----
    double lsum = 0.0;
    {
        const int row = t >> 1, hseg = (t & 1) * 32;
        const int grow = rowbase + row;
        if (grow < n_rows) {
            const int k = ((int*)(smem + OFF_KIDX))[row];
            const float4* wp = (const float4*)(g_embT + (size_t)k * DD + hseg);
            const float4* xr = (const float4*)(x + (size_t)grow * DD + hseg);
            float4* qo = (float4*)(out_q + (size_t)grow * DD + hseg);
            #pragma unroll
            for (int j = 0; j < 8; j++) {
                float4 qv = wp[j];
                float4 xv = xr[j];
                qo[j] = qv;
                float e0 = qv.x - xv.x, e1 = qv.y - xv.y;
                float e2 = qv.z - xv.z, e3 = qv.w - xv.w;
                lsum += (double)(e0 * e0 + e1 * e1 + e2 * e2 + e3 * e3);
            }
        }
    }

    // ---- loss reduction -> atomic; last block finalizes + resets ----
    #pragma unroll
    for (int off = 16; off; off >>= 1) lsum += __shfl_down_sync(0xffffffffu, lsum, off);
    double* sred = (double*)(smem + OFF_SRED);
    if (lane == 0) sred[w] = lsum;
    __syncthreads();
    if (t == 0) {
        double v = 0.0;
        #pragma unroll
        for (int i = 0; i < 8; i++) v += sred[i];
        atomicAdd(&g_loss_sum, v);
        __threadfence();
        unsigned prev = atomicAdd(&g_ctr, 1u);
        if (prev == gridDim.x - 1) {
            __threadfence();
            double total = atomicAdd(&g_loss_sum, 0.0);
            *out_loss = (float)(1.25 * total * inv_count);
            g_loss_sum = 0.0;
            g_ctr = 0u;
        }
    }
}

extern "C" void kernel_launch(void* const* d_in, const int* in_sizes, int n_in,
                              void* d_out, int out_size)
{
    const float* x   = (const float*)d_in[0];   // [N, 64]
    const float* emb = (const float*)d_in[1];   // [64, 512]

    const int n_rows = in_sizes[0] / DD;
    float* out      = (float*)d_out;
    float* out_q    = out;
    float* out_idx  = out + (size_t)n_rows * DD;
    float* out_loss = out_idx + n_rows;

    cudaFuncSetAttribute(vq_main_kernel,
                         cudaFuncAttributeMaxDynamicSharedMemorySize, SMEM_TOTAL);

    int grid = (n_rows + BN - 1) / BN;   // 512

    vq_pre_kernel<<<16, 128>>>(emb);
    vq_main_kernel<<<grid, TPB, SMEM_TOTAL>>>(x, out_q, out_idx, out_loss,
                                              n_rows, 1.0 / ((double)n_rows * (double)DD));
}